// round 4
// baseline (speedup 1.0000x reference)
#include <cuda_runtime.h>
#include <math.h>

#define BB 4
#define DD 32
#define HH 512
#define WW 512
#define HWP (HH * WW)
#define KK 16
#define DELTA_A 0.1f
#define DELTA_R 1.0f
#define ALPHA 1.0f
#define BETA 1.0f
#define GAMMA 0.001f

#define ITER 4
#define TPB 256

// Scratch: per (b, k) hinged-sum and mask-count
__device__ float g_att[BB * KK];
__device__ float g_cnt[BB * KK];

__global__ void zero_kernel() {
    int i = threadIdx.x;
    if (i < BB * KK) {
        g_att[i] = 0.0f;
        g_cnt[i] = 0.0f;
    }
}

__global__ __launch_bounds__(TPB) void main_kernel(
    const float* __restrict__ emb,
    const int* __restrict__ target,
    const int* __restrict__ centers)
{
    __shared__ float Esh[KK * DD];
    __shared__ float En2[KK];
    __shared__ int   lab[KK];
    __shared__ float red_att[KK];
    __shared__ float red_cnt[KK];

    const int b   = blockIdx.y;
    const int tid = threadIdx.x;

    // Load center embeddings E[k][d] into shared
    for (int idx = tid; idx < KK * DD; idx += TPB) {
        int k = idx / DD, d = idx % DD;
        int cy = centers[(b * KK + k) * 2 + 0];
        int cx = centers[(b * KK + k) * 2 + 1];
        Esh[k * DD + d] = emb[(size_t)b * DD * HWP + (size_t)d * HWP + cy * WW + cx];
    }
    if (tid < KK) {
        int cy = centers[(b * KK + tid) * 2 + 0];
        int cx = centers[(b * KK + tid) * 2 + 1];
        lab[tid] = target[b * HWP + cy * WW + cx];
        red_att[tid] = 0.0f;
        red_cnt[tid] = 0.0f;
    }
    __syncthreads();
    if (tid < KK) {
        // n2: rounded squares, sequential adds (contraction-proof)
        float s = 0.0f;
        #pragma unroll
        for (int d = 0; d < DD; d++) {
            float e = Esh[tid * DD + d];
            s = __fadd_rn(s, __fmul_rn(e, e));
        }
        En2[tid] = s;
    }
    __syncthreads();

    // Hoist labels to registers (uniform per block)
    int labr[KK];
    #pragma unroll
    for (int k = 0; k < KK; k++) labr[k] = lab[k];

    float att_acc[KK];
    float cnt_acc[KK];
    #pragma unroll
    for (int k = 0; k < KK; k++) { att_acc[k] = 0.0f; cnt_acc[k] = 0.0f; }

    const float* embb = emb + (size_t)b * DD * HWP;
    const int*   tgtb = target + b * HWP;
    const int base = blockIdx.x * (TPB * ITER);

    #pragma unroll
    for (int it = 0; it < ITER; it++) {
        const int p = base + it * TPB + tid;
        const int t = tgtb[p];

        float x[DD];
        float xn2 = 0.0f;
        #pragma unroll
        for (int d = 0; d < DD; d++) {
            x[d] = embb[(size_t)d * HWP + p];
        }
        #pragma unroll
        for (int d = 0; d < DD; d++) {
            float q = x[d] * x[d];
            xn2 = xn2 + q;
        }

        // Only centers whose label matches this pixel contribute
        #pragma unroll
        for (int k = 0; k < KK; k++) {
            if (labr[k] == t) {
                float dot = 0.0f;
                #pragma unroll
                for (int d = 0; d < DD; d++) {
                    dot = fmaf(Esh[k * DD + d], x[d], dot);
                }
                float d2  = (En2[k] + xn2) - 2.0f * dot;
                float nrm = (d2 > 0.0f) ? sqrtf(d2) : 0.0f;
                att_acc[k] += fmaxf(nrm - DELTA_A, 0.0f);
                cnt_acc[k] += 1.0f;
            }
        }
    }

    // Warp reduction -> shared -> global
    #pragma unroll
    for (int k = 0; k < KK; k++) {
        float a = att_acc[k];
        float c = cnt_acc[k];
        #pragma unroll
        for (int off = 16; off > 0; off >>= 1) {
            a += __shfl_down_sync(0xFFFFFFFFu, a, off);
            c += __shfl_down_sync(0xFFFFFFFFu, c, off);
        }
        if ((tid & 31) == 0) {
            if (a != 0.0f) atomicAdd(&red_att[k], a);
            if (c != 0.0f) atomicAdd(&red_cnt[k], c);
        }
    }
    __syncthreads();
    if (tid < KK) {
        if (red_att[tid] != 0.0f) atomicAdd(&g_att[b * KK + tid], red_att[tid]);
        if (red_cnt[tid] != 0.0f) atomicAdd(&g_cnt[b * KK + tid], red_cnt[tid]);
    }
}

__global__ __launch_bounds__(256) void finalize_kernel(
    const float* __restrict__ emb,
    const int* __restrict__ target,
    const int* __restrict__ centers,
    float* __restrict__ res)
{
    __shared__ float E[BB][KK][DD];       // 8 KB
    __shared__ float n2[BB][KK];          // sequential sums of rounded squares
    __shared__ float v[BB][KK * KK];      // relu(DELTA_R - norm) for every pair
    __shared__ float s_rep_sh[BB];
    __shared__ float s_reg_sh[BB];
    __shared__ float s_att_sh[BB];

    const int tid = threadIdx.x;

    // Load E
    for (int idx = tid; idx < BB * KK * DD; idx += blockDim.x) {
        int b = idx / (KK * DD);
        int k = (idx / DD) % KK;
        int d = idx % DD;
        int cy = centers[(b * KK + k) * 2 + 0];
        int cx = centers[(b * KK + k) * 2 + 1];
        E[b][k][d] = emb[(size_t)b * DD * HWP + (size_t)d * HWP + cy * WW + cx];
    }
    __syncthreads();

    // n2: emulate eager XLA sum(E*E, axis=-1):
    //   separate mul kernel  -> individually ROUNDED squares
    //   serial reduce emitter -> SEQUENTIAL adds, ascending d
    // All via __f*_rn intrinsics so nvcc cannot contract into FFMA.
    if (tid < BB * KK) {
        int b = tid / KK, k = tid % KK;
        float s = 0.0f;
        #pragma unroll
        for (int d = 0; d < DD; d++) {
            float e = E[b][k][d];
            s = __fadd_rn(s, __fmul_rn(e, e));
        }
        n2[b][k] = s;
    }
    __syncthreads();

    // All pairs: dot via sequential FFMA chain ascending d (cublas-style);
    // d2 via explicit rounded ops so nvcc cannot re-contract anything.
    for (int idx = tid; idx < BB * KK * KK; idx += blockDim.x) {
        int b = idx / (KK * KK);
        int i = (idx / KK) % KK;
        int j = idx % KK;
        float dot = 0.0f;
        #pragma unroll
        for (int d = 0; d < DD; d++) {
            dot = __fmaf_rn(E[b][i][d], E[b][j][d], dot);
        }
        float s   = __fadd_rn(n2[b][i], n2[b][j]);
        float t   = __fmul_rn(2.0f, dot);
        float d2  = __fadd_rn(s, -t);
        float nrm = (d2 > 0.0f) ? sqrtf(d2) : 0.0f;   // _safe_sqrt(relu(d2))
        v[b][i * KK + j] = fmaxf(__fadd_rn(DELTA_R, -nrm), 0.0f);
    }
    __syncthreads();

    // Per-image ordered reductions (one thread per image, sequential index order)
    if (tid < BB) {
        int b = tid;
        float s = 0.0f;
        for (int m = 0; m < KK * KK; m++) s = __fadd_rn(s, v[b][m]);
        s_rep_sh[b] = __fadd_rn(s, -(float)KK * DELTA_R);

        float sg = 0.0f;
        for (int k = 0; k < KK; k++) {
            float t = n2[b][k];
            sg = __fadd_rn(sg, (t > 0.0f) ? sqrtf(t) : 0.0f);
        }
        s_reg_sh[b] = sg;

        float sa = 0.0f;
        for (int k = 0; k < KK; k++) {
            float cnt = g_cnt[b * KK + k];
            float denom = fmaxf(cnt - 1.0f, 1.0f);
            sa = __fadd_rn(sa, __fdiv_rn(g_att[b * KK + k], denom));
        }
        s_att_sh[b] = sa;
    }
    __syncthreads();

    if (tid == 0) {
        const float div_att = (float)KK;
        const float div_rep = (float)(KK * (KK - 1));
        const float div_reg = (float)KK;
        float att = 0.0f, rep = 0.0f, reg = 0.0f;
        for (int b = 0; b < BB; b++) {
            att = __fdiv_rn(__fadd_rn(att, s_att_sh[b]), div_att);
            rep = __fdiv_rn(__fadd_rn(rep, s_rep_sh[b]), div_rep);
            reg = __fdiv_rn(__fadd_rn(reg, s_reg_sh[b]), div_reg);
        }
        float loss = __fadd_rn(__fadd_rn(__fmul_rn(ALPHA, att), __fmul_rn(BETA, rep)),
                               __fmul_rn(GAMMA, reg));
        res[0] = loss;
        res[1] = att;
        res[2] = rep;
    }
}

extern "C" void kernel_launch(void* const* d_in, const int* in_sizes, int n_in,
                              void* d_out, int out_size) {
    const float* emb     = (const float*)d_in[0];
    const int*   target  = (const int*)d_in[1];
    const int*   centers = (const int*)d_in[2];
    float* res = (float*)d_out;

    zero_kernel<<<1, 64>>>();

    dim3 grid(HWP / (TPB * ITER), BB, 1);
    main_kernel<<<grid, TPB>>>(emb, target, centers);

    finalize_kernel<<<1, 256>>>(emb, target, centers, res);
}

// round 5
// speedup vs baseline: 1.4316x; 1.4316x over previous
#include <cuda_runtime.h>
#include <math.h>

#define BB 4
#define DD 32
#define HH 512
#define WW 512
#define HWP (HH * WW)
#define KK 16
#define DELTA_A 0.1f
#define DELTA_R 1.0f
#define ALPHA 1.0f
#define BETA 1.0f
#define GAMMA 0.001f

#define TPB 256
#define PXT 4                     // pixels per thread (float4)
#define NBLK (HWP / (TPB * PXT))  // 256 blocks per image

// Per-block partial sums (written every run by every block -> no pre-zero needed)
__device__ float g_part_att[BB][NBLK][KK];
__device__ float g_part_cnt[BB][NBLK][KK];

__global__ __launch_bounds__(TPB) void main_kernel(
    const float* __restrict__ emb,
    const int* __restrict__ target,
    const int* __restrict__ centers)
{
    __shared__ float Esh[17 * 33];   // padded: row stride 33 (conflict-free), row 16 = dummy
    __shared__ float En2[17];
    __shared__ int   lab[KK];
    __shared__ float w_att[8][17];   // per-warp exclusive accumulators
    __shared__ float w_cnt[8][17];

    const int b    = blockIdx.y;
    const int tid  = threadIdx.x;
    const int wid  = tid >> 5;
    const int lane = tid & 31;

    // Load center embeddings into padded shared
    for (int idx = tid; idx < KK * DD; idx += TPB) {
        int k = idx / DD, d = idx % DD;
        int cy = centers[(b * KK + k) * 2 + 0];
        int cx = centers[(b * KK + k) * 2 + 1];
        Esh[k * 33 + d] = emb[(size_t)b * DD * HWP + (size_t)d * HWP + cy * WW + cx];
    }
    if (tid < 33) Esh[16 * 33 + tid] = 0.0f;   // dummy row
    if (tid < KK) {
        int cy = centers[(b * KK + tid) * 2 + 0];
        int cx = centers[(b * KK + tid) * 2 + 1];
        lab[tid] = target[b * HWP + cy * WW + cx];
    }
    for (int idx = tid; idx < 8 * 17; idx += TPB) {
        w_att[idx / 17][idx % 17] = 0.0f;
        w_cnt[idx / 17][idx % 17] = 0.0f;
    }
    __syncthreads();
    if (tid < KK) {
        float s = 0.0f;
        #pragma unroll
        for (int d = 0; d < DD; d++) {
            float e = Esh[tid * 33 + d];
            s = __fadd_rn(s, __fmul_rn(e, e));
        }
        En2[tid] = s;
    }
    if (tid == 16) En2[16] = 0.0f;
    __syncthreads();

    int labr[KK];
    #pragma unroll
    for (int k = 0; k < KK; k++) labr[k] = lab[k];

    const int p0 = (blockIdx.x * TPB + tid) * PXT;
    const float* embb = emb + (size_t)b * DD * HWP;

    // Targets for the 4 pixels
    const int4 t4 = *reinterpret_cast<const int4*>(target + b * HWP + p0);

    // Match masks over centers
    unsigned mA = 0, mB = 0, mC = 0, mD = 0;
    #pragma unroll
    for (int k = 0; k < KK; k++) {
        unsigned bit = 1u << k;
        if (labr[k] == t4.x) mA |= bit;
        if (labr[k] == t4.y) mB |= bit;
        if (labr[k] == t4.z) mC |= bit;
        if (labr[k] == t4.w) mD |= bit;
    }
    int kA = mA ? (__ffs(mA) - 1) : 16;
    int kB = mB ? (__ffs(mB) - 1) : 16;
    int kC = mC ? (__ffs(mC) - 1) : 16;
    int kD = mD ? (__ffs(mD) - 1) : 16;

    const float4* xp = reinterpret_cast<const float4*>(embb) + (p0 >> 2);

    float xnA = 0.f, xnB = 0.f, xnC = 0.f, xnD = 0.f;
    float dA  = 0.f, dB  = 0.f, dC  = 0.f, dD  = 0.f;

    #pragma unroll
    for (int d = 0; d < DD; d++) {
        float4 x = xp[d * (HWP / 4)];
        xnA = fmaf(x.x, x.x, xnA);
        xnB = fmaf(x.y, x.y, xnB);
        xnC = fmaf(x.z, x.z, xnC);
        xnD = fmaf(x.w, x.w, xnD);
        dA = fmaf(Esh[kA * 33 + d], x.x, dA);
        dB = fmaf(Esh[kB * 33 + d], x.y, dB);
        dC = fmaf(Esh[kC * 33 + d], x.z, dC);
        dD = fmaf(Esh[kD * 33 + d], x.w, dD);
    }

    // Hinge values (0 for dummy k=16 since we gate on validity below anyway)
    float vA, vB, vC, vD;
    {
        float d2, nrm;
        d2 = (En2[kA] + xnA) - 2.0f * dA; nrm = (d2 > 0.f) ? sqrtf(d2) : 0.f;
        vA = (kA < 16) ? fmaxf(nrm - DELTA_A, 0.f) : 0.f;
        d2 = (En2[kB] + xnB) - 2.0f * dB; nrm = (d2 > 0.f) ? sqrtf(d2) : 0.f;
        vB = (kB < 16) ? fmaxf(nrm - DELTA_A, 0.f) : 0.f;
        d2 = (En2[kC] + xnC) - 2.0f * dC; nrm = (d2 > 0.f) ? sqrtf(d2) : 0.f;
        vC = (kC < 16) ? fmaxf(nrm - DELTA_A, 0.f) : 0.f;
        d2 = (En2[kD] + xnD) - 2.0f * dD; nrm = (d2 > 0.f) ? sqrtf(d2) : 0.f;
        vD = (kD < 16) ? fmaxf(nrm - DELTA_A, 0.f) : 0.f;
    }

    // Accumulate (uniform control flow; warp-uniform fast path, else atomics)
    float* att_row = w_att[wid];
    float* cnt_row = w_cnt[wid];
    #pragma unroll
    for (int s = 0; s < 4; s++) {
        int   k = (s == 0) ? kA : (s == 1) ? kB : (s == 2) ? kC : kD;
        float v = (s == 0) ? vA : (s == 1) ? vB : (s == 2) ? vC : vD;
        int k0 = __shfl_sync(0xFFFFFFFFu, k, 0);
        bool uni = __all_sync(0xFFFFFFFFu, k == k0);
        if (uni) {
            float sum = v;
            #pragma unroll
            for (int off = 16; off > 0; off >>= 1)
                sum += __shfl_down_sync(0xFFFFFFFFu, sum, off);
            if (lane == 0 && k0 < 16) {
                att_row[k0] += sum;
                cnt_row[k0] += 32.0f;
            }
        } else {
            if (k < 16) {
                atomicAdd(&att_row[k], v);
                atomicAdd(&cnt_row[k], 1.0f);
            }
        }
    }

    // Rare slow path: additional matching centers beyond the first (generality)
    unsigned exA = mA & (mA - 1), exB = mB & (mB - 1);
    unsigned exC = mC & (mC - 1), exD = mD & (mD - 1);
    if (exA | exB | exC | exD) {
        #pragma unroll
        for (int s = 0; s < 4; s++) {
            unsigned ex = (s == 0) ? exA : (s == 1) ? exB : (s == 2) ? exC : exD;
            float xn    = (s == 0) ? xnA : (s == 1) ? xnB : (s == 2) ? xnC : xnD;
            int p = p0 + s;
            while (ex) {
                int k = __ffs(ex) - 1;
                ex &= ex - 1;
                float dot = 0.0f;
                for (int d = 0; d < DD; d++)
                    dot = fmaf(Esh[k * 33 + d], embb[(size_t)d * HWP + p], dot);
                float d2  = (En2[k] + xn) - 2.0f * dot;
                float nrm = (d2 > 0.f) ? sqrtf(d2) : 0.f;
                atomicAdd(&att_row[k], fmaxf(nrm - DELTA_A, 0.f));
                atomicAdd(&cnt_row[k], 1.0f);
            }
        }
    }

    __syncthreads();
    if (tid < KK) {
        float sa = 0.f, sc = 0.f;
        #pragma unroll
        for (int w = 0; w < 8; w++) { sa += w_att[w][tid]; sc += w_cnt[w][tid]; }
        g_part_att[b][blockIdx.x][tid] = sa;
        g_part_cnt[b][blockIdx.x][tid] = sc;
    }
}

__global__ __launch_bounds__(512) void finalize_kernel(
    const float* __restrict__ emb,
    const int* __restrict__ target,
    const int* __restrict__ centers,
    float* __restrict__ res)
{
    __shared__ float E[BB][KK][DD];
    __shared__ float n2[BB][KK];
    __shared__ float v[BB][KK * KK];
    __shared__ float att_k[BB][KK];
    __shared__ float cnt_k[BB][KK];
    __shared__ float part_a[64][8];
    __shared__ float part_c[64][8];
    __shared__ float s_rep_sh[BB];
    __shared__ float s_reg_sh[BB];
    __shared__ float s_att_sh[BB];

    const int tid = threadIdx.x;

    // Stage 1: partial-sum reduction of per-block partials (512 threads = 64 groups x 8)
    {
        int g = tid >> 3, sub = tid & 7;
        int b = g >> 4, k = g & 15;
        float sa = 0.f, sc = 0.f;
        #pragma unroll 4
        for (int i = sub; i < NBLK; i += 8) {
            sa += g_part_att[b][i][k];
            sc += g_part_cnt[b][i][k];
        }
        part_a[g][sub] = sa;
        part_c[g][sub] = sc;
    }

    // Load E
    for (int idx = tid; idx < BB * KK * DD; idx += blockDim.x) {
        int b = idx / (KK * DD);
        int k = (idx / DD) % KK;
        int d = idx % DD;
        int cy = centers[(b * KK + k) * 2 + 0];
        int cx = centers[(b * KK + k) * 2 + 1];
        E[b][k][d] = emb[(size_t)b * DD * HWP + (size_t)d * HWP + cy * WW + cx];
    }
    __syncthreads();

    if (tid < 64) {
        int b = tid >> 4, k = tid & 15;
        float sa = 0.f, sc = 0.f;
        #pragma unroll
        for (int s = 0; s < 8; s++) { sa += part_a[tid][s]; sc += part_c[tid][s]; }
        att_k[b][k] = sa;
        cnt_k[b][k] = sc;

        // n2: eager-XLA order — individually ROUNDED squares, SEQUENTIAL adds
        float s = 0.0f;
        #pragma unroll
        for (int d = 0; d < DD; d++) {
            float e = E[b][k][d];
            s = __fadd_rn(s, __fmul_rn(e, e));
        }
        n2[b][k] = s;
    }
    __syncthreads();

    // All pairs: sequential FFMA chain (gemm order), explicit rounded ops
    for (int idx = tid; idx < BB * KK * KK; idx += blockDim.x) {
        int b = idx / (KK * KK);
        int i = (idx / KK) % KK;
        int j = idx % KK;
        float dot = 0.0f;
        #pragma unroll
        for (int d = 0; d < DD; d++) {
            dot = __fmaf_rn(E[b][i][d], E[b][j][d], dot);
        }
        float s   = __fadd_rn(n2[b][i], n2[b][j]);
        float t   = __fmul_rn(2.0f, dot);
        float d2  = __fadd_rn(s, -t);
        float nrm = (d2 > 0.0f) ? sqrtf(d2) : 0.0f;
        v[b][i * KK + j] = fmaxf(__fadd_rn(DELTA_R, -nrm), 0.0f);
    }
    __syncthreads();

    // Per-image ordered reductions
    if (tid < BB) {
        int b = tid;
        float s = 0.0f;
        for (int m = 0; m < KK * KK; m++) s = __fadd_rn(s, v[b][m]);
        s_rep_sh[b] = __fadd_rn(s, -(float)KK * DELTA_R);

        float sg = 0.0f;
        for (int k = 0; k < KK; k++) {
            float t = n2[b][k];
            sg = __fadd_rn(sg, (t > 0.0f) ? sqrtf(t) : 0.0f);
        }
        s_reg_sh[b] = sg;

        float sa = 0.0f;
        for (int k = 0; k < KK; k++) {
            float cnt = cnt_k[b][k];
            float denom = fmaxf(cnt - 1.0f, 1.0f);
            sa = __fadd_rn(sa, __fdiv_rn(att_k[b][k], denom));
        }
        s_att_sh[b] = sa;
    }
    __syncthreads();

    if (tid == 0) {
        const float div_att = (float)KK;
        const float div_rep = (float)(KK * (KK - 1));
        const float div_reg = (float)KK;
        float att = 0.0f, rep = 0.0f, reg = 0.0f;
        for (int b = 0; b < BB; b++) {
            att = __fdiv_rn(__fadd_rn(att, s_att_sh[b]), div_att);
            rep = __fdiv_rn(__fadd_rn(rep, s_rep_sh[b]), div_rep);
            reg = __fdiv_rn(__fadd_rn(reg, s_reg_sh[b]), div_reg);
        }
        float loss = __fadd_rn(__fadd_rn(__fmul_rn(ALPHA, att), __fmul_rn(BETA, rep)),
                               __fmul_rn(GAMMA, reg));
        res[0] = loss;
        res[1] = att;
        res[2] = rep;
    }
}

extern "C" void kernel_launch(void* const* d_in, const int* in_sizes, int n_in,
                              void* d_out, int out_size) {
    const float* emb     = (const float*)d_in[0];
    const int*   target  = (const int*)d_in[1];
    const int*   centers = (const int*)d_in[2];
    float* res = (float*)d_out;

    dim3 grid(NBLK, BB, 1);
    main_kernel<<<grid, TPB>>>(emb, target, centers);

    finalize_kernel<<<1, 512>>>(emb, target, centers, res);
}